// round 1
// baseline (speedup 1.0000x reference)
#include <cuda_runtime.h>
#include <math.h>

#define NMAX 50000
#define EMAX 800000
#define D    128

// ---------------- scratch (static device globals; no allocation) -------------
__device__ int   g_deg_out[NMAX];
__device__ int   g_deg_in [NMAX];
__device__ float g_ns[NMAX];
__device__ float g_nd[NMAX];
__device__ int   g_row_off[NMAX + 1];
__device__ int   g_cursor[NMAX];
__device__ int   g_csr_src[EMAX];
__device__ float g_y [NMAX * D];   // post-GEMM features (gather source)
__device__ float g_fa[NMAX * D];   // ping
__device__ float g_fb[NMAX * D];   // pong

// ---------------- graph preprocessing ----------------------------------------
__global__ void zero_kernel(int n) {
    int i = blockIdx.x * blockDim.x + threadIdx.x;
    if (i < n) { g_deg_out[i] = 0; g_deg_in[i] = 0; g_cursor[i] = 0; }
}

__global__ void count_kernel(const int* __restrict__ src,
                             const int* __restrict__ dst, int e) {
    int i = blockIdx.x * blockDim.x + threadIdx.x;
    if (i < e) {
        atomicAdd(&g_deg_out[src[i]], 1);
        atomicAdd(&g_deg_in [dst[i]], 1);
    }
}

__global__ void norm_kernel(int n) {
    int i = blockIdx.x * blockDim.x + threadIdx.x;
    if (i < n) {
        int dof = g_deg_out[i]; if (dof < 1) dof = 1;
        int din = g_deg_in [i]; if (din < 1) din = 1;
        g_ns[i] = rsqrtf((float)dof);
        g_nd[i] = rsqrtf((float)din);
    }
}

// exclusive scan of g_deg_in into g_row_off (single block, 1024 threads)
__global__ void scan_kernel(int n) {
    __shared__ int s[1024];
    int tid = threadIdx.x;
    int carry = 0;
    for (int base = 0; base < n; base += 1024) {
        int i = base + tid;
        int v = (i < n) ? g_deg_in[i] : 0;
        s[tid] = v;
        __syncthreads();
        for (int off = 1; off < 1024; off <<= 1) {
            int t = (tid >= off) ? s[tid - off] : 0;
            __syncthreads();
            s[tid] += t;
            __syncthreads();
        }
        if (i < n) g_row_off[i] = carry + s[tid] - v;
        int tot = s[1023];
        __syncthreads();   // everyone done reading s before next overwrite
        carry += tot;
    }
    if (tid == 0) g_row_off[n] = carry;
}

__global__ void fill_kernel(const int* __restrict__ src,
                            const int* __restrict__ dst, int e) {
    int i = blockIdx.x * blockDim.x + threadIdx.x;
    if (i < e) {
        int d = dst[i];
        int pos = g_row_off[d] + atomicAdd(&g_cursor[d], 1);
        g_csr_src[pos] = src[i];
    }
}

// deterministic summation order: sort each node's src list ascending
__global__ void sort_kernel(int n) {
    int i = blockIdx.x * blockDim.x + threadIdx.x;
    if (i >= n) return;
    int a = g_row_off[i], b = g_row_off[i + 1];
    for (int p = a + 1; p < b; p++) {
        int key = g_csr_src[p];
        int q = p - 1;
        while (q >= a && g_csr_src[q] > key) { g_csr_src[q + 1] = g_csr_src[q]; q--; }
        g_csr_src[q + 1] = key;
    }
}

// ---------------- GEMM: y = (x * ns) @ W  ------------------------------------
// blockDim = 128 (4 warps). Each block processes 16-row tiles (grid-stride).
// W (128x128 f32, 64KB) resident in smem, x tile (16x128) in smem.
// Thread (cg=lane, rg=warp): 4 rows x 4 cols = 16 accumulators;
// per k: one LDS.128 of W (16B) feeds 16 FMAs + 4 broadcast x reads.
__global__ void gemm_kernel(const float* __restrict__ x,
                            const float* __restrict__ W,
                            float* __restrict__ y, int n) {
    extern __shared__ float sm[];
    float* sW = sm;            // 128*128
    float* sx = sm + D * D;    // 16*128

    for (int i = threadIdx.x; i < D * D; i += blockDim.x) sW[i] = W[i];
    __syncthreads();

    int ntiles = (n + 15) >> 4;
    int cg = threadIdx.x & 31;   // column group (lane)
    int rg = threadIdx.x >> 5;   // row group (warp)
    int c0 = cg * 4;

    for (int tile = blockIdx.x; tile < ntiles; tile += gridDim.x) {
        int r0 = tile << 4;
        for (int i = threadIdx.x; i < 16 * D; i += blockDim.x) {
            int lr = i >> 7, c = i & 127;
            int gr = r0 + lr;
            sx[i] = (gr < n) ? x[gr * D + c] * g_ns[gr] : 0.f;
        }
        __syncthreads();

        float4 a0 = {0,0,0,0}, a1 = {0,0,0,0}, a2 = {0,0,0,0}, a3 = {0,0,0,0};
        const float* xr = sx + (rg * 4) * D;
        #pragma unroll 8
        for (int k = 0; k < D; k++) {
            float4 w = *(const float4*)(sW + k * D + c0);
            float x0 = xr[k], x1 = xr[D + k], x2 = xr[2 * D + k], x3 = xr[3 * D + k];
            a0.x += x0 * w.x; a0.y += x0 * w.y; a0.z += x0 * w.z; a0.w += x0 * w.w;
            a1.x += x1 * w.x; a1.y += x1 * w.y; a1.z += x1 * w.z; a1.w += x1 * w.w;
            a2.x += x2 * w.x; a2.y += x2 * w.y; a2.z += x2 * w.z; a2.w += x2 * w.w;
            a3.x += x3 * w.x; a3.y += x3 * w.y; a3.z += x3 * w.z; a3.w += x3 * w.w;
        }
        int gr = r0 + rg * 4;
        if (gr + 0 < n) *(float4*)(y + (gr + 0) * D + c0) = a0;
        if (gr + 1 < n) *(float4*)(y + (gr + 1) * D + c0) = a1;
        if (gr + 2 < n) *(float4*)(y + (gr + 2) * D + c0) = a2;
        if (gr + 3 < n) *(float4*)(y + (gr + 3) * D + c0) = a3;
        __syncthreads();
    }
}

// ---------------- aggregation: out = relu(nd * segsum(y[src]) + b) -----------
// warp per node; lane handles 4 contiguous cols (float4). Optional threshold out.
__global__ void agg_kernel(const float* __restrict__ y,
                           const float* __restrict__ bias,
                           float* __restrict__ out,
                           float* __restrict__ out_thr, int n) {
    int gw = (blockIdx.x * blockDim.x + threadIdx.x) >> 5;
    int lane = threadIdx.x & 31;
    if (gw >= n) return;
    int s0 = g_row_off[gw], s1 = g_row_off[gw + 1];
    float4 acc = {0,0,0,0};
    int e = s0;
    for (; e + 1 < s1; e += 2) {
        int sa = g_csr_src[e], sb = g_csr_src[e + 1];
        float4 va = *(const float4*)(y + sa * D + lane * 4);
        float4 vb = *(const float4*)(y + sb * D + lane * 4);
        acc.x += va.x; acc.y += va.y; acc.z += va.z; acc.w += va.w;
        acc.x += vb.x; acc.y += vb.y; acc.z += vb.z; acc.w += vb.w;
    }
    if (e < s1) {
        int sa = g_csr_src[e];
        float4 va = *(const float4*)(y + sa * D + lane * 4);
        acc.x += va.x; acc.y += va.y; acc.z += va.z; acc.w += va.w;
    }
    float ndv = g_nd[gw];
    float4 bb = *(const float4*)(bias + lane * 4);
    float4 r;
    r.x = fmaxf(acc.x * ndv + bb.x, 0.f);
    r.y = fmaxf(acc.y * ndv + bb.y, 0.f);
    r.z = fmaxf(acc.z * ndv + bb.z, 0.f);
    r.w = fmaxf(acc.w * ndv + bb.w, 0.f);
    *(float4*)(out + gw * D + lane * 4) = r;
    if (out_thr) {
        float4 t;
        t.x = r.x >= 0.5f ? 1.f : 0.f;
        t.y = r.y >= 0.5f ? 1.f : 0.f;
        t.z = r.z >= 0.5f ? 1.f : 0.f;
        t.w = r.w >= 0.5f ? 1.f : 0.f;
        *(float4*)(out_thr + gw * D + lane * 4) = t;
    }
}

// ---------------- host launcher ----------------------------------------------
extern "C" void kernel_launch(void* const* d_in, const int* in_sizes, int n_in,
                              void* d_out, int out_size) {
    const float* in_feat = (const float*)d_in[0];
    const int*   src     = (const int*)d_in[1];
    const int*   dst     = (const int*)d_in[2];
    int N = in_sizes[0] / D;
    int E = in_sizes[1];

    // weights (16384 elems) vs biases (128 elems) — robust to either metadata order
    const float* W[5]; const float* B[5];
    int nw = 0, nb = 0;
    for (int i = 3; i < n_in; i++) {
        if (in_sizes[i] >= D * D) { if (nw < 5) W[nw++] = (const float*)d_in[i]; }
        else                      { if (nb < 5) B[nb++] = (const float*)d_in[i]; }
    }

    float* out = (float*)d_out;
    float* out_thr = (out_size >= 2 * N * D) ? out + (size_t)N * D : nullptr;

    // resolve device-global addresses for ping-pong
    float* fa; float* fb; float* ybuf;
    cudaGetSymbolAddress((void**)&fa,   g_fa);
    cudaGetSymbolAddress((void**)&fb,   g_fb);
    cudaGetSymbolAddress((void**)&ybuf, g_y);

    const int TB = 256;
    int nb_nodes = (N + TB - 1) / TB;
    int nb_edges = (E + TB - 1) / TB;

    // graph preprocessing (once per launch)
    zero_kernel <<<nb_nodes, TB>>>(N);
    count_kernel<<<nb_edges, TB>>>(src, dst, E);
    norm_kernel <<<nb_nodes, TB>>>(N);
    scan_kernel <<<1, 1024>>>(N);
    fill_kernel <<<nb_edges, TB>>>(src, dst, E);
    sort_kernel <<<nb_nodes, TB>>>(N);

    // GEMM config: 72KB dynamic smem -> opt-in
    size_t smem = (size_t)(D * D + 16 * D) * sizeof(float);
    cudaFuncSetAttribute(gemm_kernel, cudaFuncAttributeMaxDynamicSharedMemorySize,
                         (int)smem);
    int ntiles = (N + 15) / 16;
    int ggrid = 444;                 // ~3 blocks/SM, grid-stride over tiles
    if (ggrid > ntiles) ggrid = ntiles;

    int agrid = (N * 32 + TB - 1) / TB;   // warp per node, 8 warps/block

    const float* cur = in_feat;
    for (int l = 0; l < 5; l++) {
        gemm_kernel<<<ggrid, 128, smem>>>(cur, W[l], ybuf, N);
        float* nxt = (l == 4) ? out : ((l & 1) ? fb : fa);
        float* thr = (l == 4) ? out_thr : nullptr;
        agg_kernel<<<agrid, TB>>>(ybuf, B[l], nxt, thr, N);
        cur = nxt;
    }
}

// round 2
// speedup vs baseline: 1.0537x; 1.0537x over previous
#include <cuda_runtime.h>
#include <math.h>

#define NMAX 50000
#define EMAX 800000
#define D    128
#define SXS  132              // padded sx row stride (floats), kills bank conflicts
#define TILE_R 64

// ---------------- scratch (static device globals; no allocation) -------------
__device__ int   g_deg_out[NMAX];
__device__ int   g_deg_in [NMAX];
__device__ float g_ns[NMAX];
__device__ float g_nd[NMAX];
__device__ int   g_row_off[NMAX + 1];
__device__ int   g_cursor[NMAX];
__device__ int   g_csr_src[EMAX];
__device__ int   g_bsum[256];
__device__ int   g_boff[256];
__device__ int   g_total;
__device__ float g_y [NMAX * D];   // post-GEMM features (gather source)
__device__ float g_fa[NMAX * D];   // ping
__device__ float g_fb[NMAX * D];   // pong

// ---------------- packed fp32x2 helpers ---------------------------------------
__device__ __forceinline__ unsigned long long ffma2(unsigned long long a,
                                                    unsigned long long b,
                                                    unsigned long long c) {
    asm("fma.rn.f32x2 %0, %1, %2, %0;" : "+l"(c) : "l"(a), "l"(b));
    return c;
}
__device__ __forceinline__ unsigned long long pack2(float x) {
    unsigned long long r;
    asm("mov.b64 %0, {%1, %1};" : "=l"(r) : "f"(x));
    return r;
}
__device__ __forceinline__ float2 unpack2(unsigned long long v) {
    float2 f;
    asm("mov.b64 {%0, %1}, %2;" : "=f"(f.x), "=f"(f.y) : "l"(v));
    return f;
}

// ---------------- graph preprocessing ----------------------------------------
__global__ void zero_kernel(int n) {
    int i = blockIdx.x * blockDim.x + threadIdx.x;
    if (i < n) { g_deg_out[i] = 0; g_deg_in[i] = 0; g_cursor[i] = 0; }
}

__global__ void count_kernel(const int* __restrict__ src,
                             const int* __restrict__ dst, int e) {
    int i = blockIdx.x * blockDim.x + threadIdx.x;
    if (i < e) {
        atomicAdd(&g_deg_out[src[i]], 1);
        atomicAdd(&g_deg_in [dst[i]], 1);
    }
}

__global__ void norm_kernel(int n) {
    int i = blockIdx.x * blockDim.x + threadIdx.x;
    if (i < n) {
        int dof = g_deg_out[i]; if (dof < 1) dof = 1;
        int din = g_deg_in [i]; if (din < 1) din = 1;
        g_ns[i] = rsqrtf((float)dof);
        g_nd[i] = rsqrtf((float)din);
    }
}

// ---- fast 3-phase exclusive scan of g_deg_in into g_row_off ------------------
__global__ void scan1_kernel(int n) {
    int tid = threadIdx.x, lane = tid & 31, warp = tid >> 5;
    int i = blockIdx.x * 256 + tid;
    int v = (i < n) ? g_deg_in[i] : 0;
    int x = v;
    #pragma unroll
    for (int off = 1; off < 32; off <<= 1) {
        int t = __shfl_up_sync(0xffffffffu, x, off);
        if (lane >= off) x += t;
    }
    __shared__ int ws[8];
    if (lane == 31) ws[warp] = x;
    __syncthreads();
    if (tid == 0) {
        int c = 0;
        #pragma unroll
        for (int j = 0; j < 8; j++) { int t = ws[j]; ws[j] = c; c += t; }
        g_bsum[blockIdx.x] = c;
    }
    __syncthreads();
    if (i < n) g_row_off[i] = ws[warp] + x - v;     // block-local exclusive
}

__global__ void scan2_kernel(int nb) {
    int tid = threadIdx.x, lane = tid & 31, warp = tid >> 5;
    int v = (tid < nb) ? g_bsum[tid] : 0;
    int x = v;
    #pragma unroll
    for (int off = 1; off < 32; off <<= 1) {
        int t = __shfl_up_sync(0xffffffffu, x, off);
        if (lane >= off) x += t;
    }
    __shared__ int ws[8];
    if (lane == 31) ws[warp] = x;
    __syncthreads();
    if (tid == 0) {
        int c = 0;
        #pragma unroll
        for (int j = 0; j < 8; j++) { int t = ws[j]; ws[j] = c; c += t; }
        g_total = c;
    }
    __syncthreads();
    if (tid < nb) g_boff[tid] = ws[warp] + x - v;
}

__global__ void scan3_kernel(int n) {
    int i = blockIdx.x * blockDim.x + threadIdx.x;
    if (i < n)       g_row_off[i] += g_boff[i >> 8];
    else if (i == n) g_row_off[n]  = g_total;
}

__global__ void fill_kernel(const int* __restrict__ src,
                            const int* __restrict__ dst, int e) {
    int i = blockIdx.x * blockDim.x + threadIdx.x;
    if (i < e) {
        int d = dst[i];
        int pos = g_row_off[d] + atomicAdd(&g_cursor[d], 1);
        g_csr_src[pos] = src[i];
    }
}

// deterministic summation order: sort each node's src list ascending
__global__ void sort_kernel(int n) {
    int i = blockIdx.x * blockDim.x + threadIdx.x;
    if (i >= n) return;
    int a = g_row_off[i], b = g_row_off[i + 1];
    for (int p = a + 1; p < b; p++) {
        int key = g_csr_src[p];
        int q = p - 1;
        while (q >= a && g_csr_src[q] > key) { g_csr_src[q + 1] = g_csr_src[q]; q--; }
        g_csr_src[q + 1] = key;
    }
}

// ---------------- GEMM: y = (x * ns) @ W  (packed fp32x2) ---------------------
// 256 threads = 8 warps, 64-row tiles. W (128x128) + sx (64x132) in smem.
// Thread: 4 rows x 8 cols (16 u64 fp32x2 accumulators). Columns: half-warp
// (16 lanes) x 8 cols = 128. Rows: warp*8 + half*4 + {0..3}.
__global__ void gemm_kernel(const float* __restrict__ x,
                            const float* __restrict__ W,
                            float* __restrict__ y, int n) {
    extern __shared__ float sm[];
    float* sW = sm;                 // 128*128
    float* sx = sm + D * D;         // 64*132

    for (int i = threadIdx.x; i < D * D; i += 256) sW[i] = W[i];

    int lane = threadIdx.x & 31;
    int warp = threadIdx.x >> 5;
    int half = lane >> 4;
    int l16  = lane & 15;
    int c0   = l16 * 8;
    int rowgroup = warp * 8 + half * 4;

    int ntiles = (n + TILE_R - 1) / TILE_R;

    for (int tile = blockIdx.x; tile < ntiles; tile += gridDim.x) {
        int r0 = tile * TILE_R;
        __syncthreads();
        // load x tile scaled by ns: 64 rows x 128 cols, float4 per thread-iter
        for (int idx = threadIdx.x; idx < TILE_R * 32; idx += 256) {
            int lr = idx >> 5;
            int cq = (idx & 31) * 4;
            int gr = r0 + lr;
            float4 v = {0.f, 0.f, 0.f, 0.f};
            if (gr < n) {
                v = *(const float4*)(x + (size_t)gr * D + cq);
                float s = g_ns[gr];
                v.x *= s; v.y *= s; v.z *= s; v.w *= s;
            }
            *(float4*)(sx + lr * SXS + cq) = v;
        }
        __syncthreads();

        unsigned long long acc[4][4];
        #pragma unroll
        for (int j = 0; j < 4; j++)
            #pragma unroll
            for (int p = 0; p < 4; p++) acc[j][p] = 0ull;

        const float* xr = sx + rowgroup * SXS;
        #pragma unroll 4
        for (int k = 0; k < D; k += 2) {
            ulonglong2 wa0 = *(const ulonglong2*)(sW + k * D + c0);
            ulonglong2 wa1 = *(const ulonglong2*)(sW + k * D + c0 + 4);
            ulonglong2 wb0 = *(const ulonglong2*)(sW + (k + 1) * D + c0);
            ulonglong2 wb1 = *(const ulonglong2*)(sW + (k + 1) * D + c0 + 4);
            #pragma unroll
            for (int j = 0; j < 4; j++) {
                float2 xv = *(const float2*)(xr + j * SXS + k);
                unsigned long long xa = pack2(xv.x);
                acc[j][0] = ffma2(xa, wa0.x, acc[j][0]);
                acc[j][1] = ffma2(xa, wa0.y, acc[j][1]);
                acc[j][2] = ffma2(xa, wa1.x, acc[j][2]);
                acc[j][3] = ffma2(xa, wa1.y, acc[j][3]);
                unsigned long long xb = pack2(xv.y);
                acc[j][0] = ffma2(xb, wb0.x, acc[j][0]);
                acc[j][1] = ffma2(xb, wb0.y, acc[j][1]);
                acc[j][2] = ffma2(xb, wb1.x, acc[j][2]);
                acc[j][3] = ffma2(xb, wb1.y, acc[j][3]);
            }
        }

        #pragma unroll
        for (int j = 0; j < 4; j++) {
            int gr = r0 + rowgroup + j;
            if (gr < n) {
                float2 p0 = unpack2(acc[j][0]);
                float2 p1 = unpack2(acc[j][1]);
                float2 p2 = unpack2(acc[j][2]);
                float2 p3 = unpack2(acc[j][3]);
                float4 o0 = {p0.x, p0.y, p1.x, p1.y};
                float4 o1 = {p2.x, p2.y, p3.x, p3.y};
                *(float4*)(y + (size_t)gr * D + c0)     = o0;
                *(float4*)(y + (size_t)gr * D + c0 + 4) = o1;
            }
        }
    }
}

// ---------------- aggregation: out = relu(nd * segsum(y[src]) + b) -----------
__global__ void agg_kernel(const float* __restrict__ y,
                           const float* __restrict__ bias,
                           float* __restrict__ out,
                           float* __restrict__ out_thr, int n) {
    int gw = (blockIdx.x * blockDim.x + threadIdx.x) >> 5;
    int lane = threadIdx.x & 31;
    if (gw >= n) return;
    int s0 = g_row_off[gw], s1 = g_row_off[gw + 1];
    float4 acc = {0, 0, 0, 0};
    int e = s0;
    for (; e + 4 <= s1; e += 4) {
        int i0 = g_csr_src[e + 0];
        int i1 = g_csr_src[e + 1];
        int i2 = g_csr_src[e + 2];
        int i3 = g_csr_src[e + 3];
        float4 v0 = *(const float4*)(y + (size_t)i0 * D + lane * 4);
        float4 v1 = *(const float4*)(y + (size_t)i1 * D + lane * 4);
        float4 v2 = *(const float4*)(y + (size_t)i2 * D + lane * 4);
        float4 v3 = *(const float4*)(y + (size_t)i3 * D + lane * 4);
        acc.x += v0.x + v1.x + v2.x + v3.x;
        acc.y += v0.y + v1.y + v2.y + v3.y;
        acc.z += v0.z + v1.z + v2.z + v3.z;
        acc.w += v0.w + v1.w + v2.w + v3.w;
    }
    for (; e < s1; e++) {
        int i0 = g_csr_src[e];
        float4 v0 = *(const float4*)(y + (size_t)i0 * D + lane * 4);
        acc.x += v0.x; acc.y += v0.y; acc.z += v0.z; acc.w += v0.w;
    }
    float ndv = g_nd[gw];
    float4 bb = *(const float4*)(bias + lane * 4);
    float4 r;
    r.x = fmaxf(acc.x * ndv + bb.x, 0.f);
    r.y = fmaxf(acc.y * ndv + bb.y, 0.f);
    r.z = fmaxf(acc.z * ndv + bb.z, 0.f);
    r.w = fmaxf(acc.w * ndv + bb.w, 0.f);
    *(float4*)(out + (size_t)gw * D + lane * 4) = r;
    if (out_thr) {
        float4 t;
        t.x = r.x >= 0.5f ? 1.f : 0.f;
        t.y = r.y >= 0.5f ? 1.f : 0.f;
        t.z = r.z >= 0.5f ? 1.f : 0.f;
        t.w = r.w >= 0.5f ? 1.f : 0.f;
        *(float4*)(out_thr + (size_t)gw * D + lane * 4) = t;
    }
}

// ---------------- host launcher ----------------------------------------------
extern "C" void kernel_launch(void* const* d_in, const int* in_sizes, int n_in,
                              void* d_out, int out_size) {
    const float* in_feat = (const float*)d_in[0];
    const int*   src     = (const int*)d_in[1];
    const int*   dst     = (const int*)d_in[2];
    int N = in_sizes[0] / D;
    int E = in_sizes[1];

    const float* W[5]; const float* B[5];
    int nw = 0, nb = 0;
    for (int i = 3; i < n_in; i++) {
        if (in_sizes[i] >= D * D) { if (nw < 5) W[nw++] = (const float*)d_in[i]; }
        else                      { if (nb < 5) B[nb++] = (const float*)d_in[i]; }
    }

    float* out = (float*)d_out;
    float* out_thr = (out_size >= 2 * N * D) ? out + (size_t)N * D : nullptr;

    float* fa; float* fb; float* ybuf;
    cudaGetSymbolAddress((void**)&fa,   g_fa);
    cudaGetSymbolAddress((void**)&fb,   g_fb);
    cudaGetSymbolAddress((void**)&ybuf, g_y);

    const int TB = 256;
    int nb_nodes = (N + TB - 1) / TB;
    int nb_edges = (E + TB - 1) / TB;
    int nscan = nb_nodes;                       // 256-elem scan blocks

    zero_kernel <<<nb_nodes, TB>>>(N);
    count_kernel<<<nb_edges, TB>>>(src, dst, E);
    norm_kernel <<<nb_nodes, TB>>>(N);
    scan1_kernel<<<nscan, 256>>>(N);
    scan2_kernel<<<1, 256>>>(nscan);
    scan3_kernel<<<(N + 1 + TB - 1) / TB, TB>>>(N);
    fill_kernel <<<nb_edges, TB>>>(src, dst, E);
    sort_kernel <<<nb_nodes, TB>>>(N);

    // GEMM config: W (64KB) + sx (64*132*4 = 33.8KB) ≈ 98KB dynamic smem
    size_t smem = (size_t)(D * D + TILE_R * SXS) * sizeof(float);
    cudaFuncSetAttribute(gemm_kernel, cudaFuncAttributeMaxDynamicSharedMemorySize,
                         (int)smem);
    int ntiles = (N + TILE_R - 1) / TILE_R;
    int ggrid = 296;                 // 2 blocks/SM
    if (ggrid > ntiles) ggrid = ntiles;

    int agrid = (N * 32 + TB - 1) / TB;   // warp per node

    const float* cur = in_feat;
    for (int l = 0; l < 5; l++) {
        gemm_kernel<<<ggrid, 256, smem>>>(cur, W[l], ybuf, N);
        float* nxt = (l == 4) ? out : ((l & 1) ? fb : fa);
        float* thr = (l == 4) ? out_thr : nullptr;
        agg_kernel<<<agrid, TB>>>(ybuf, B[l], nxt, thr, N);
        cur = nxt;
    }
}

// round 4
// speedup vs baseline: 1.4494x; 1.3755x over previous
#include <cuda_runtime.h>
#include <math.h>
#include <stdint.h>

#define NMAX 50000
#define EMAX 800000
#define D    128
#define SAP  68            // A smem row pad (floats)
#define SWP  132           // W smem row pad (floats)

// ---------------- scratch (static device globals; no allocation) -------------
__device__ int   g_deg_out[NMAX];
__device__ int   g_deg_in [NMAX];
__device__ float g_ns[NMAX];
__device__ float g_nd[NMAX];
__device__ int   g_row_off[NMAX + 1];
__device__ int   g_cursor[NMAX];
__device__ int   g_csr_src[EMAX];
__device__ int   g_bsum[256];
__device__ int   g_boff[256];
__device__ int   g_total;
__device__ float g_y [NMAX * D];        // post-GEMM features (gather source)
__device__ float g_fa[NMAX * D];        // ping
__device__ float g_fb[NMAX * D];        // pong
__device__ float g_wt_hi[5 * D * D];    // W^T, tf32-high part, [n][k]
__device__ float g_wt_lo[5 * D * D];    // W^T, residual part,  [n][k]

// ---------------- helpers ------------------------------------------------------
__device__ __forceinline__ float to_tf32(float x) {
    uint32_t u;
    asm("cvt.rna.tf32.f32 %0, %1;" : "=r"(u) : "f"(x));
    return __uint_as_float(u);
}

#define MMA_TF32(c, a, b)                                                       \
    asm volatile("mma.sync.aligned.m16n8k8.row.col.f32.tf32.tf32.f32 "          \
        "{%0,%1,%2,%3}, {%4,%5,%6,%7}, {%8,%9}, {%0,%1,%2,%3};"                 \
        : "+f"((c)[0]), "+f"((c)[1]), "+f"((c)[2]), "+f"((c)[3])                 \
        : "r"((a)[0]), "r"((a)[1]), "r"((a)[2]), "r"((a)[3]),                    \
          "r"((b)[0]), "r"((b)[1]))

// ---------------- graph preprocessing ----------------------------------------
__global__ void zero_kernel(int n) {
    int i = blockIdx.x * blockDim.x + threadIdx.x;
    if (i < n) { g_deg_out[i] = 0; g_deg_in[i] = 0; g_cursor[i] = 0; }
}

__global__ void count_kernel(const int* __restrict__ src,
                             const int* __restrict__ dst, int e) {
    int i = blockIdx.x * blockDim.x + threadIdx.x;
    if (i < e) {
        atomicAdd(&g_deg_out[src[i]], 1);
        atomicAdd(&g_deg_in [dst[i]], 1);
    }
}

__global__ void norm_kernel(int n) {
    int i = blockIdx.x * blockDim.x + threadIdx.x;
    if (i < n) {
        int dof = g_deg_out[i]; if (dof < 1) dof = 1;
        int din = g_deg_in [i]; if (din < 1) din = 1;
        g_ns[i] = rsqrtf((float)dof);
        g_nd[i] = rsqrtf((float)din);
    }
}

__global__ void scan1_kernel(int n) {
    int tid = threadIdx.x, lane = tid & 31, warp = tid >> 5;
    int i = blockIdx.x * 256 + tid;
    int v = (i < n) ? g_deg_in[i] : 0;
    int x = v;
    #pragma unroll
    for (int off = 1; off < 32; off <<= 1) {
        int t = __shfl_up_sync(0xffffffffu, x, off);
        if (lane >= off) x += t;
    }
    __shared__ int ws[8];
    if (lane == 31) ws[warp] = x;
    __syncthreads();
    if (tid == 0) {
        int c = 0;
        #pragma unroll
        for (int j = 0; j < 8; j++) { int t = ws[j]; ws[j] = c; c += t; }
        g_bsum[blockIdx.x] = c;
    }
    __syncthreads();
    if (i < n) g_row_off[i] = ws[warp] + x - v;
}

__global__ void scan2_kernel(int nb) {
    int tid = threadIdx.x, lane = tid & 31, warp = tid >> 5;
    int v = (tid < nb) ? g_bsum[tid] : 0;
    int x = v;
    #pragma unroll
    for (int off = 1; off < 32; off <<= 1) {
        int t = __shfl_up_sync(0xffffffffu, x, off);
        if (lane >= off) x += t;
    }
    __shared__ int ws[8];
    if (lane == 31) ws[warp] = x;
    __syncthreads();
    if (tid == 0) {
        int c = 0;
        #pragma unroll
        for (int j = 0; j < 8; j++) { int t = ws[j]; ws[j] = c; c += t; }
        g_total = c;
    }
    __syncthreads();
    if (tid < nb) g_boff[tid] = ws[warp] + x - v;
}

__global__ void scan3_kernel(int n) {
    int i = blockIdx.x * blockDim.x + threadIdx.x;
    if (i < n)       g_row_off[i] += g_boff[i >> 8];
    else if (i == n) g_row_off[n]  = g_total;
}

__global__ void fill_kernel(const int* __restrict__ src,
                            const int* __restrict__ dst, int e) {
    int i = blockIdx.x * blockDim.x + threadIdx.x;
    if (i < e) {
        int d = dst[i];
        int pos = g_row_off[d] + atomicAdd(&g_cursor[d], 1);
        g_csr_src[pos] = src[i];
    }
}

__global__ void sort_kernel(int n) {
    int i = blockIdx.x * blockDim.x + threadIdx.x;
    if (i >= n) return;
    int a = g_row_off[i], b = g_row_off[i + 1];
    for (int p = a + 1; p < b; p++) {
        int key = g_csr_src[p];
        int q = p - 1;
        while (q >= a && g_csr_src[q] > key) { g_csr_src[q + 1] = g_csr_src[q]; q--; }
        g_csr_src[q + 1] = key;
    }
}

// ---------------- W^T + tf32 hi/lo split (once per launch) --------------------
__global__ void wprep_kernel(const float* __restrict__ W0, const float* __restrict__ W1,
                             const float* __restrict__ W2, const float* __restrict__ W3,
                             const float* __restrict__ W4) {
    const float* Ws[5] = {W0, W1, W2, W3, W4};
    const float* W = Ws[blockIdx.z];
    __shared__ float t[32][33];
    int kb = blockIdx.x * 32, nb = blockIdx.y * 32;
    int tx = threadIdx.x, ty = threadIdx.y;
    #pragma unroll
    for (int j = 0; j < 4; j++)
        t[ty + 8 * j][tx] = W[(kb + ty + 8 * j) * D + nb + tx];
    __syncthreads();
    size_t base = (size_t)blockIdx.z * D * D;
    #pragma unroll
    for (int j = 0; j < 4; j++) {
        float v = t[tx][ty + 8 * j];
        float hi = to_tf32(v);
        size_t idx = base + (size_t)(nb + ty + 8 * j) * D + kb + tx;
        g_wt_hi[idx] = hi;
        g_wt_lo[idx] = v - hi;
    }
}

// ---------------- tensor-core GEMM via mma.sync (3xTF32) ----------------------
// 256 threads = 8 warps (4x2). Block tile 128x128, warp tile 32x64.
// smem: sWh/sWl full W^T (128 x 132 pad), sAh/sAl A K-chunk (128 x 68 pad).
__global__ __launch_bounds__(256, 1)
void gemm_mma_kernel(const float* __restrict__ x,
                     const float* __restrict__ wth,
                     const float* __restrict__ wtl,
                     float* __restrict__ y, int n) {
    extern __shared__ float sm[];
    float* sWh = sm;                       // 128*132 = 16896
    float* sWl = sm + 16896;
    float* sAh = sm + 2 * 16896;           // 128*68 = 8704
    float* sAl = sm + 2 * 16896 + 8704;

    int tid = threadIdx.x;
    // load W^T hi/lo (padded rows)
    for (int idx = tid; idx < D * 32; idx += 256) {
        int r = idx >> 5, q = (idx & 31) * 4;
        float4 h = *(const float4*)(wth + (size_t)r * D + q);
        float4 l = *(const float4*)(wtl + (size_t)r * D + q);
        *(float4*)(sWh + r * SWP + q) = h;
        *(float4*)(sWl + r * SWP + q) = l;
    }

    int lane = tid & 31, wid = tid >> 5;
    int wm = wid & 3;            // warp row group (0..3) -> 32 rows each
    int wn = wid >> 2;           // warp col group (0..1) -> 64 cols each
    int g = lane >> 2, t = lane & 3;

    int ntiles = (n + 127) >> 7;

    for (int tile = blockIdx.x; tile < ntiles; tile += gridDim.x) {
        int r0 = tile << 7;
        float acc[2][8][4];
        #pragma unroll
        for (int mt = 0; mt < 2; mt++)
            #pragma unroll
            for (int nt = 0; nt < 8; nt++)
                #pragma unroll
                for (int j = 0; j < 4; j++) acc[mt][nt][j] = 0.f;

        #pragma unroll
        for (int c = 0; c < 2; c++) {
            __syncthreads();   // previous chunk fully consumed (and W loaded)
            // load A chunk: rows 0..127, cols [c*64, c*64+64), split hi/lo
            for (int idx = tid; idx < 128 * 16; idx += 256) {
                int row = idx >> 4, q = (idx & 15) * 4;
                int gr = r0 + row;
                float4 v = {0.f, 0.f, 0.f, 0.f};
                if (gr < n) {
                    v = *(const float4*)(x + (size_t)gr * D + c * 64 + q);
                    float s = g_ns[gr];
                    v.x *= s; v.y *= s; v.z *= s; v.w *= s;
                }
                float4 h, l;
                h.x = to_tf32(v.x); l.x = v.x - h.x;
                h.y = to_tf32(v.y); l.y = v.y - h.y;
                h.z = to_tf32(v.z); l.z = v.z - h.z;
                h.w = to_tf32(v.w); l.w = v.w - h.w;
                *(float4*)(sAh + row * SAP + q) = h;
                *(float4*)(sAl + row * SAP + q) = l;
            }
            __syncthreads();

            #pragma unroll
            for (int ks = 0; ks < 8; ks++) {
                int kA = ks * 8;           // col in A chunk
                int kW = c * 64 + ks * 8;  // col in W rows
                // A fragments (m16n8k8 row-major mapping)
                uint32_t ah[2][4], al[2][4];
                #pragma unroll
                for (int mt = 0; mt < 2; mt++) {
                    int rb = wm * 32 + mt * 16;
                    int i00 = (rb + g) * SAP + kA + t;
                    int i10 = (rb + g + 8) * SAP + kA + t;
                    ah[mt][0] = __float_as_uint(sAh[i00]);
                    ah[mt][1] = __float_as_uint(sAh[i10]);
                    ah[mt][2] = __float_as_uint(sAh[i00 + 4]);
                    ah[mt][3] = __float_as_uint(sAh[i10 + 4]);
                    al[mt][0] = __float_as_uint(sAl[i00]);
                    al[mt][1] = __float_as_uint(sAl[i10]);
                    al[mt][2] = __float_as_uint(sAl[i00 + 4]);
                    al[mt][3] = __float_as_uint(sAl[i10 + 4]);
                }
                #pragma unroll
                for (int nt = 0; nt < 8; nt++) {
                    int nb = (wn * 64 + nt * 8 + g) * SWP + kW + t;
                    uint32_t bh[2], bl[2];
                    bh[0] = __float_as_uint(sWh[nb]);
                    bh[1] = __float_as_uint(sWh[nb + 4]);
                    bl[0] = __float_as_uint(sWl[nb]);
                    bl[1] = __float_as_uint(sWl[nb + 4]);
                    #pragma unroll
                    for (int mt = 0; mt < 2; mt++) {
                        MMA_TF32(acc[mt][nt], ah[mt], bh);
                        MMA_TF32(acc[mt][nt], ah[mt], bl);
                        MMA_TF32(acc[mt][nt], al[mt], bh);
                    }
                }
            }
        }

        // epilogue: c0,c1 -> row g, cols 2t,2t+1 ; c2,c3 -> row g+8
        #pragma unroll
        for (int mt = 0; mt < 2; mt++) {
            int rlo = r0 + wm * 32 + mt * 16 + g;
            int rhi = rlo + 8;
            #pragma unroll
            for (int nt = 0; nt < 8; nt++) {
                int cb = wn * 64 + nt * 8 + 2 * t;
                if (rlo < n) {
                    float2 o = {acc[mt][nt][0], acc[mt][nt][1]};
                    *(float2*)(y + (size_t)rlo * D + cb) = o;
                }
                if (rhi < n) {
                    float2 o = {acc[mt][nt][2], acc[mt][nt][3]};
                    *(float2*)(y + (size_t)rhi * D + cb) = o;
                }
            }
        }
    }
}

// ---------------- aggregation: out = relu(nd * segsum(y[src]) + b) -----------
__global__ void agg_kernel(const float* __restrict__ y,
                           const float* __restrict__ bias,
                           float* __restrict__ out,
                           float* __restrict__ out_thr, int n) {
    int gw = (blockIdx.x * blockDim.x + threadIdx.x) >> 5;
    int lane = threadIdx.x & 31;
    if (gw >= n) return;
    int s0 = g_row_off[gw], s1 = g_row_off[gw + 1];
    float4 acc = {0, 0, 0, 0};
    int e = s0;
    for (; e + 4 <= s1; e += 4) {
        int i0 = g_csr_src[e + 0];
        int i1 = g_csr_src[e + 1];
        int i2 = g_csr_src[e + 2];
        int i3 = g_csr_src[e + 3];
        float4 v0 = *(const float4*)(y + (size_t)i0 * D + lane * 4);
        float4 v1 = *(const float4*)(y + (size_t)i1 * D + lane * 4);
        float4 v2 = *(const float4*)(y + (size_t)i2 * D + lane * 4);
        float4 v3 = *(const float4*)(y + (size_t)i3 * D + lane * 4);
        acc.x += v0.x + v1.x + v2.x + v3.x;
        acc.y += v0.y + v1.y + v2.y + v3.y;
        acc.z += v0.z + v1.z + v2.z + v3.z;
        acc.w += v0.w + v1.w + v2.w + v3.w;
    }
    for (; e < s1; e++) {
        int i0 = g_csr_src[e];
        float4 v0 = *(const float4*)(y + (size_t)i0 * D + lane * 4);
        acc.x += v0.x; acc.y += v0.y; acc.z += v0.z; acc.w += v0.w;
    }
    float ndv = g_nd[gw];
    float4 bb = *(const float4*)(bias + lane * 4);
    float4 r;
    r.x = fmaxf(acc.x * ndv + bb.x, 0.f);
    r.y = fmaxf(acc.y * ndv + bb.y, 0.f);
    r.z = fmaxf(acc.z * ndv + bb.z, 0.f);
    r.w = fmaxf(acc.w * ndv + bb.w, 0.f);
    *(float4*)(out + (size_t)gw * D + lane * 4) = r;
    if (out_thr) {
        float4 t;
        t.x = r.x >= 0.5f ? 1.f : 0.f;
        t.y = r.y >= 0.5f ? 1.f : 0.f;
        t.z = r.z >= 0.5f ? 1.f : 0.f;
        t.w = r.w >= 0.5f ? 1.f : 0.f;
        *(float4*)(out_thr + (size_t)gw * D + lane * 4) = t;
    }
}

// ---------------- host launcher ----------------------------------------------
extern "C" void kernel_launch(void* const* d_in, const int* in_sizes, int n_in,
                              void* d_out, int out_size) {
    const float* in_feat = (const float*)d_in[0];
    const int*   src     = (const int*)d_in[1];
    const int*   dst     = (const int*)d_in[2];
    int N = in_sizes[0] / D;
    int E = in_sizes[1];

    const float* W[5]; const float* B[5];
    int nw = 0, nb = 0;
    for (int i = 3; i < n_in; i++) {
        if (in_sizes[i] >= D * D) { if (nw < 5) W[nw++] = (const float*)d_in[i]; }
        else                      { if (nb < 5) B[nb++] = (const float*)d_in[i]; }
    }

    float* out = (float*)d_out;
    float* out_thr = (out_size >= 2 * N * D) ? out + (size_t)N * D : nullptr;

    float* fa; float* fb; float* ybuf; float* wth; float* wtl;
    cudaGetSymbolAddress((void**)&fa,   g_fa);
    cudaGetSymbolAddress((void**)&fb,   g_fb);
    cudaGetSymbolAddress((void**)&ybuf, g_y);
    cudaGetSymbolAddress((void**)&wth,  g_wt_hi);
    cudaGetSymbolAddress((void**)&wtl,  g_wt_lo);

    const int TB = 256;
    int nb_nodes = (N + TB - 1) / TB;
    int nb_edges = (E + TB - 1) / TB;
    int nscan = nb_nodes;

    zero_kernel <<<nb_nodes, TB>>>(N);
    count_kernel<<<nb_edges, TB>>>(src, dst, E);
    norm_kernel <<<nb_nodes, TB>>>(N);
    scan1_kernel<<<nscan, 256>>>(N);
    scan2_kernel<<<1, 256>>>(nscan);
    scan3_kernel<<<(N + 1 + TB - 1) / TB, TB>>>(N);
    fill_kernel <<<nb_edges, TB>>>(src, dst, E);
    sort_kernel <<<nb_nodes, TB>>>(N);

    wprep_kernel<<<dim3(4, 4, 5), dim3(32, 8)>>>(W[0], W[1], W[2], W[3], W[4]);

    // smem: 2*(128*132) + 2*(128*68) floats = 51200 floats = 204800 bytes
    size_t smem = (size_t)(2 * D * SWP + 2 * D * SAP) * sizeof(float);
    cudaFuncSetAttribute(gemm_mma_kernel,
                         cudaFuncAttributeMaxDynamicSharedMemorySize, (int)smem);
    int ntiles = (N + 127) / 128;
    int ggrid = 148;
    if (ggrid > ntiles) ggrid = ntiles;

    int agrid = (N * 32 + TB - 1) / TB;

    const float* cur = in_feat;
    for (int l = 0; l < 5; l++) {
        gemm_mma_kernel<<<ggrid, 256, smem>>>(cur, wth + (size_t)l * D * D,
                                              wtl + (size_t)l * D * D, ybuf, N);
        float* nxt = (l == 4) ? out : ((l & 1) ? fb : fa);
        float* thr = (l == 4) ? out_thr : nullptr;
        agg_kernel<<<agrid, TB>>>(ybuf, B[l], nxt, thr, N);
        cur = nxt;
    }
}

// round 5
// speedup vs baseline: 1.4796x; 1.0209x over previous
#include <cuda_runtime.h>
#include <math.h>
#include <stdint.h>

#define NMAX 50000
#define EMAX 800000
#define D    128
#define SAP  68            // A smem row pad (floats)
#define SWP  132           // W smem row pad (floats)

// ---------------- scratch (static device globals; no allocation) -------------
__device__ int   g_deg_out[NMAX];
__device__ int   g_deg_in [NMAX];
__device__ float g_ns[NMAX];
__device__ float g_nd[NMAX];
__device__ int   g_row_off[NMAX + 1];
__device__ int   g_cursor[NMAX];
__device__ int   g_csr_src[EMAX];
__device__ int   g_bsum[256];
__device__ int   g_boff[256];
__device__ int   g_total;
__device__ float g_y [NMAX * D];        // post-GEMM features (gather source)
__device__ float g_fa[NMAX * D];        // ping
__device__ float g_fb[NMAX * D];        // pong
__device__ float g_wt_hi[5 * D * D];    // W^T, tf32-high part, [n][k]
__device__ float g_wt_lo[5 * D * D];    // W^T, residual part,  [n][k]

// ---------------- helpers ------------------------------------------------------
__device__ __forceinline__ float to_tf32(float x) {
    uint32_t u;
    asm("cvt.rna.tf32.f32 %0, %1;" : "=r"(u) : "f"(x));
    return __uint_as_float(u);
}

#define MMA_TF32(c, a, b)                                                       \
    asm volatile("mma.sync.aligned.m16n8k8.row.col.f32.tf32.tf32.f32 "          \
        "{%0,%1,%2,%3}, {%4,%5,%6,%7}, {%8,%9}, {%0,%1,%2,%3};"                 \
        : "+f"((c)[0]), "+f"((c)[1]), "+f"((c)[2]), "+f"((c)[3])                 \
        : "r"((a)[0]), "r"((a)[1]), "r"((a)[2]), "r"((a)[3]),                    \
          "r"((b)[0]), "r"((b)[1]))

// ---------------- graph preprocessing ----------------------------------------
__global__ void zero_kernel(int n) {
    int i = blockIdx.x * blockDim.x + threadIdx.x;
    if (i < n) { g_deg_out[i] = 0; g_deg_in[i] = 0; g_cursor[i] = 0; }
}

__global__ void count_kernel(const int* __restrict__ src,
                             const int* __restrict__ dst, int e) {
    int i = blockIdx.x * blockDim.x + threadIdx.x;
    if (i < e) {
        atomicAdd(&g_deg_out[src[i]], 1);
        atomicAdd(&g_deg_in [dst[i]], 1);
    }
}

__global__ void norm_kernel(int n) {
    int i = blockIdx.x * blockDim.x + threadIdx.x;
    if (i < n) {
        int dof = g_deg_out[i]; if (dof < 1) dof = 1;
        int din = g_deg_in [i]; if (din < 1) din = 1;
        g_ns[i] = rsqrtf((float)dof);
        g_nd[i] = rsqrtf((float)din);
    }
}

__global__ void scan1_kernel(int n) {
    int tid = threadIdx.x, lane = tid & 31, warp = tid >> 5;
    int i = blockIdx.x * 256 + tid;
    int v = (i < n) ? g_deg_in[i] : 0;
    int x = v;
    #pragma unroll
    for (int off = 1; off < 32; off <<= 1) {
        int t = __shfl_up_sync(0xffffffffu, x, off);
        if (lane >= off) x += t;
    }
    __shared__ int ws[8];
    if (lane == 31) ws[warp] = x;
    __syncthreads();
    if (tid == 0) {
        int c = 0;
        #pragma unroll
        for (int j = 0; j < 8; j++) { int t = ws[j]; ws[j] = c; c += t; }
        g_bsum[blockIdx.x] = c;
    }
    __syncthreads();
    if (i < n) g_row_off[i] = ws[warp] + x - v;
}

__global__ void scan2_kernel(int nb) {
    int tid = threadIdx.x, lane = tid & 31, warp = tid >> 5;
    int v = (tid < nb) ? g_bsum[tid] : 0;
    int x = v;
    #pragma unroll
    for (int off = 1; off < 32; off <<= 1) {
        int t = __shfl_up_sync(0xffffffffu, x, off);
        if (lane >= off) x += t;
    }
    __shared__ int ws[8];
    if (lane == 31) ws[warp] = x;
    __syncthreads();
    if (tid == 0) {
        int c = 0;
        #pragma unroll
        for (int j = 0; j < 8; j++) { int t = ws[j]; ws[j] = c; c += t; }
        g_total = c;
    }
    __syncthreads();
    if (tid < nb) g_boff[tid] = ws[warp] + x - v;
}

__global__ void scan3_kernel(int n) {
    int i = blockIdx.x * blockDim.x + threadIdx.x;
    if (i < n)       g_row_off[i] += g_boff[i >> 8];
    else if (i == n) g_row_off[n]  = g_total;
}

__global__ void fill_kernel(const int* __restrict__ src,
                            const int* __restrict__ dst, int e) {
    int i = blockIdx.x * blockDim.x + threadIdx.x;
    if (i < e) {
        int d = dst[i];
        int pos = g_row_off[d] + atomicAdd(&g_cursor[d], 1);
        g_csr_src[pos] = src[i];
    }
}

__global__ void sort_kernel(int n) {
    int i = blockIdx.x * blockDim.x + threadIdx.x;
    if (i >= n) return;
    int a = g_row_off[i], b = g_row_off[i + 1];
    for (int p = a + 1; p < b; p++) {
        int key = g_csr_src[p];
        int q = p - 1;
        while (q >= a && g_csr_src[q] > key) { g_csr_src[q + 1] = g_csr_src[q]; q--; }
        g_csr_src[q + 1] = key;
    }
}

// ---------------- W^T + tf32 hi/lo split (once per launch) --------------------
__global__ void wprep_kernel(const float* __restrict__ W0, const float* __restrict__ W1,
                             const float* __restrict__ W2, const float* __restrict__ W3,
                             const float* __restrict__ W4) {
    const float* Ws[5] = {W0, W1, W2, W3, W4};
    const float* W = Ws[blockIdx.z];
    __shared__ float t[32][33];
    int kb = blockIdx.x * 32, nb = blockIdx.y * 32;
    int tx = threadIdx.x, ty = threadIdx.y;
    #pragma unroll
    for (int j = 0; j < 4; j++)
        t[ty + 8 * j][tx] = W[(kb + ty + 8 * j) * D + nb + tx];
    __syncthreads();
    size_t base = (size_t)blockIdx.z * D * D;
    #pragma unroll
    for (int j = 0; j < 4; j++) {
        float v = t[tx][ty + 8 * j];
        float hi = to_tf32(v);
        size_t idx = base + (size_t)(nb + ty + 8 * j) * D + kb + tx;
        g_wt_hi[idx] = hi;
        g_wt_lo[idx] = v - hi;
    }
}

// ---------------- tensor-core GEMM via mma.sync (3xTF32, prefetch) ------------
// 256 threads = 8 warps (4x2). Block tile 128x128, warp tile 32x64.
// K split in 2x64 chunks; next chunk's global loads prefetched to registers
// before the current chunk's MMA block so L2 latency hides under MMA.
__global__ __launch_bounds__(256, 1)
void gemm_mma_kernel(const float* __restrict__ x,
                     const float* __restrict__ wth,
                     const float* __restrict__ wtl,
                     float* __restrict__ y, int n) {
    extern __shared__ float sm[];
    float* sWh = sm;                       // 128*132 = 16896
    float* sWl = sm + 16896;
    float* sAh = sm + 2 * 16896;           // 128*68 = 8704
    float* sAl = sm + 2 * 16896 + 8704;

    int tid = threadIdx.x;
    // load W^T hi/lo (padded rows)
    for (int idx = tid; idx < D * 32; idx += 256) {
        int r = idx >> 5, q = (idx & 31) * 4;
        float4 h = *(const float4*)(wth + (size_t)r * D + q);
        float4 l = *(const float4*)(wtl + (size_t)r * D + q);
        *(float4*)(sWh + r * SWP + q) = h;
        *(float4*)(sWl + r * SWP + q) = l;
    }

    int lane = tid & 31, wid = tid >> 5;
    int wm = wid & 3;            // warp row group (0..3) -> 32 rows each
    int wn = wid >> 2;           // warp col group (0..1) -> 64 cols each
    int g = lane >> 2, t = lane & 3;

    // per-thread fixed (row, col) slots for A chunk loads: 8 float4 each
    int prow[8], pq[8];
    #pragma unroll
    for (int j = 0; j < 8; j++) {
        int idx = tid + 256 * j;
        prow[j] = idx >> 4;
        pq[j]   = (idx & 15) * 4;
    }

    int ntiles = (n + 127) >> 7;

    for (int tile = blockIdx.x; tile < ntiles; tile += gridDim.x) {
        int r0 = tile << 7;
        float acc[2][8][4];
        #pragma unroll
        for (int mt = 0; mt < 2; mt++)
            #pragma unroll
            for (int nt = 0; nt < 8; nt++)
                #pragma unroll
                for (int j = 0; j < 4; j++) acc[mt][nt][j] = 0.f;

        // prefetch chunk 0
        float4 pf[8];
        #pragma unroll
        for (int j = 0; j < 8; j++) {
            int gr = r0 + prow[j];
            pf[j] = (gr < n) ? *(const float4*)(x + (size_t)gr * D + pq[j])
                             : make_float4(0.f, 0.f, 0.f, 0.f);
        }

        #pragma unroll
        for (int c = 0; c < 2; c++) {
            __syncthreads();   // previous chunk fully consumed (and W loaded)
            // store prefetched chunk c into smem (hi/lo split)
            #pragma unroll
            for (int j = 0; j < 8; j++) {
                int gr = r0 + prow[j];
                float s = (gr < n) ? g_ns[gr] : 0.f;
                float4 v = pf[j];
                v.x *= s; v.y *= s; v.z *= s; v.w *= s;
                float4 h, l;
                h.x = to_tf32(v.x); l.x = v.x - h.x;
                h.y = to_tf32(v.y); l.y = v.y - h.y;
                h.z = to_tf32(v.z); l.z = v.z - h.z;
                h.w = to_tf32(v.w); l.w = v.w - h.w;
                *(float4*)(sAh + prow[j] * SAP + pq[j]) = h;
                *(float4*)(sAl + prow[j] * SAP + pq[j]) = l;
            }
            // prefetch chunk 1 (issued before MMA; completes under MMA)
            if (c == 0) {
                #pragma unroll
                for (int j = 0; j < 8; j++) {
                    int gr = r0 + prow[j];
                    pf[j] = (gr < n) ? *(const float4*)(x + (size_t)gr * D + 64 + pq[j])
                                     : make_float4(0.f, 0.f, 0.f, 0.f);
                }
            }
            __syncthreads();

            #pragma unroll
            for (int ks = 0; ks < 8; ks++) {
                int kA = ks * 8;           // col in A chunk
                int kW = c * 64 + ks * 8;  // col in W rows
                uint32_t ah[2][4], al[2][4];
                #pragma unroll
                for (int mt = 0; mt < 2; mt++) {
                    int rb = wm * 32 + mt * 16;
                    int i00 = (rb + g) * SAP + kA + t;
                    int i10 = (rb + g + 8) * SAP + kA + t;
                    ah[mt][0] = __float_as_uint(sAh[i00]);
                    ah[mt][1] = __float_as_uint(sAh[i10]);
                    ah[mt][2] = __float_as_uint(sAh[i00 + 4]);
                    ah[mt][3] = __float_as_uint(sAh[i10 + 4]);
                    al[mt][0] = __float_as_uint(sAl[i00]);
                    al[mt][1] = __float_as_uint(sAl[i10]);
                    al[mt][2] = __float_as_uint(sAl[i00 + 4]);
                    al[mt][3] = __float_as_uint(sAl[i10 + 4]);
                }
                #pragma unroll
                for (int nt = 0; nt < 8; nt++) {
                    int nb = (wn * 64 + nt * 8 + g) * SWP + kW + t;
                    uint32_t bh[2], bl[2];
                    bh[0] = __float_as_uint(sWh[nb]);
                    bh[1] = __float_as_uint(sWh[nb + 4]);
                    bl[0] = __float_as_uint(sWl[nb]);
                    bl[1] = __float_as_uint(sWl[nb + 4]);
                    #pragma unroll
                    for (int mt = 0; mt < 2; mt++) {
                        MMA_TF32(acc[mt][nt], ah[mt], bh);
                        MMA_TF32(acc[mt][nt], ah[mt], bl);
                        MMA_TF32(acc[mt][nt], al[mt], bh);
                    }
                }
            }
        }

        // epilogue: c0,c1 -> row g, cols 2t,2t+1 ; c2,c3 -> row g+8
        #pragma unroll
        for (int mt = 0; mt < 2; mt++) {
            int rlo = r0 + wm * 32 + mt * 16 + g;
            int rhi = rlo + 8;
            #pragma unroll
            for (int nt = 0; nt < 8; nt++) {
                int cb = wn * 64 + nt * 8 + 2 * t;
                if (rlo < n) {
                    float2 o = {acc[mt][nt][0], acc[mt][nt][1]};
                    *(float2*)(y + (size_t)rlo * D + cb) = o;
                }
                if (rhi < n) {
                    float2 o = {acc[mt][nt][2], acc[mt][nt][3]};
                    *(float2*)(y + (size_t)rhi * D + cb) = o;
                }
            }
        }
    }
}

// ---------------- aggregation: out = relu(nd * segsum(y[src]) + b) -----------
__global__ void agg_kernel(const float* __restrict__ y,
                           const float* __restrict__ bias,
                           float* __restrict__ out,
                           float* __restrict__ out_thr, int n) {
    int gw = (blockIdx.x * blockDim.x + threadIdx.x) >> 5;
    int lane = threadIdx.x & 31;
    if (gw >= n) return;
    int s0 = g_row_off[gw], s1 = g_row_off[gw + 1];
    float4 acc = {0, 0, 0, 0};
    int e = s0;
    for (; e + 4 <= s1; e += 4) {
        int i0 = g_csr_src[e + 0];
        int i1 = g_csr_src[e + 1];
        int i2 = g_csr_src[e + 2];
        int i3 = g_csr_src[e + 3];
        float4 v0 = *(const float4*)(y + (size_t)i0 * D + lane * 4);
        float4 v1 = *(const float4*)(y + (size_t)i1 * D + lane * 4);
        float4 v2 = *(const float4*)(y + (size_t)i2 * D + lane * 4);
        float4 v3 = *(const float4*)(y + (size_t)i3 * D + lane * 4);
        acc.x += v0.x + v1.x + v2.x + v3.x;
        acc.y += v0.y + v1.y + v2.y + v3.y;
        acc.z += v0.z + v1.z + v2.z + v3.z;
        acc.w += v0.w + v1.w + v2.w + v3.w;
    }
    for (; e < s1; e++) {
        int i0 = g_csr_src[e];
        float4 v0 = *(const float4*)(y + (size_t)i0 * D + lane * 4);
        acc.x += v0.x; acc.y += v0.y; acc.z += v0.z; acc.w += v0.w;
    }
    float ndv = g_nd[gw];
    float4 bb = *(const float4*)(bias + lane * 4);
    float4 r;
    r.x = fmaxf(acc.x * ndv + bb.x, 0.f);
    r.y = fmaxf(acc.y * ndv + bb.y, 0.f);
    r.z = fmaxf(acc.z * ndv + bb.z, 0.f);
    r.w = fmaxf(acc.w * ndv + bb.w, 0.f);
    *(float4*)(out + (size_t)gw * D + lane * 4) = r;
    if (out_thr) {
        float4 t;
        t.x = r.x >= 0.5f ? 1.f : 0.f;
        t.y = r.y >= 0.5f ? 1.f : 0.f;
        t.z = r.z >= 0.5f ? 1.f : 0.f;
        t.w = r.w >= 0.5f ? 1.f : 0.f;
        *(float4*)(out_thr + (size_t)gw * D + lane * 4) = t;
    }
}

// ---------------- host launcher ----------------------------------------------
extern "C" void kernel_launch(void* const* d_in, const int* in_sizes, int n_in,
                              void* d_out, int out_size) {
    const float* in_feat = (const float*)d_in[0];
    const int*   src     = (const int*)d_in[1];
    const int*   dst     = (const int*)d_in[2];
    int N = in_sizes[0] / D;
    int E = in_sizes[1];

    const float* W[5]; const float* B[5];
    int nw = 0, nb = 0;
    for (int i = 3; i < n_in; i++) {
        if (in_sizes[i] >= D * D) { if (nw < 5) W[nw++] = (const float*)d_in[i]; }
        else                      { if (nb < 5) B[nb++] = (const float*)d_in[i]; }
    }

    float* out = (float*)d_out;
    float* out_thr = (out_size >= 2 * N * D) ? out + (size_t)N * D : nullptr;

    float* fa; float* fb; float* ybuf; float* wth; float* wtl;
    cudaGetSymbolAddress((void**)&fa,   g_fa);
    cudaGetSymbolAddress((void**)&fb,   g_fb);
    cudaGetSymbolAddress((void**)&ybuf, g_y);
    cudaGetSymbolAddress((void**)&wth,  g_wt_hi);
    cudaGetSymbolAddress((void**)&wtl,  g_wt_lo);

    // one-time side stream + events (host objects; created outside capture on
    // the first (correctness) call, reused by every later call identically)
    static cudaStream_t s2 = nullptr;
    static cudaEvent_t evA = nullptr, evB = nullptr;
    if (!s2) {
        cudaStreamCreateWithFlags(&s2, cudaStreamNonBlocking);
        cudaEventCreateWithFlags(&evA, cudaEventDisableTiming);
        cudaEventCreateWithFlags(&evB, cudaEventDisableTiming);
    }

    const int TB = 256;
    int nb_nodes = (N + TB - 1) / TB;
    int nb_edges = (E + TB - 1) / TB;
    int nscan = nb_nodes;

    // main stream: degrees (needed by both branches)
    zero_kernel <<<nb_nodes, TB>>>(N);
    count_kernel<<<nb_edges, TB>>>(src, dst, E);
    cudaEventRecord(evA, 0);

    // side stream: CSR build (needed only by agg of layer 1)
    cudaStreamWaitEvent(s2, evA, 0);
    scan1_kernel<<<nscan, 256, 0, s2>>>(N);
    scan2_kernel<<<1, 256, 0, s2>>>(nscan);
    scan3_kernel<<<(N + 1 + TB - 1) / TB, TB, 0, s2>>>(N);
    fill_kernel <<<nb_edges, TB, 0, s2>>>(src, dst, E);
    sort_kernel <<<nb_nodes, TB, 0, s2>>>(N);
    cudaEventRecord(evB, s2);

    // main stream: norms, W prep, GEMM layer 1 (overlaps CSR build)
    norm_kernel <<<nb_nodes, TB>>>(N);
    wprep_kernel<<<dim3(4, 4, 5), dim3(32, 8)>>>(W[0], W[1], W[2], W[3], W[4]);

    size_t smem = (size_t)(2 * D * SWP + 2 * D * SAP) * sizeof(float);
    cudaFuncSetAttribute(gemm_mma_kernel,
                         cudaFuncAttributeMaxDynamicSharedMemorySize, (int)smem);
    int ntiles = (N + 127) / 128;
    int ggrid = 148;
    if (ggrid > ntiles) ggrid = ntiles;
    int agrid = (N * 32 + TB - 1) / TB;

    const float* cur = in_feat;
    for (int l = 0; l < 5; l++) {
        gemm_mma_kernel<<<ggrid, 256, smem>>>(cur, wth + (size_t)l * D * D,
                                              wtl + (size_t)l * D * D, ybuf, N);
        if (l == 0) cudaStreamWaitEvent(0, evB, 0);   // CSR ready before agg1
        float* nxt = (l == 4) ? out : ((l & 1) ? fb : fa);
        float* thr = (l == 4) ? out_thr : nullptr;
        agg_kernel<<<agrid, TB>>>(ybuf, B[l], nxt, thr, N);
        cur = nxt;
    }
}